// round 9
// baseline (speedup 1.0000x reference)
#include <cuda_runtime.h>
#include <float.h>
#include <math.h>

#define A_  64
#define B_  256
#define L_  2000
#define FC1 32
#define FC2 64
#define H_  128
#define KK  5
#define TILE 128
#define NTILE 16   // 16*128 = 2048 >= 2000
#define NTHR 256

typedef unsigned long long u64;

// ---------------- scratch (device globals; no allocation allowed) ----------
__device__ float g_U[B_ * L_ * A_];          // u[b][l][a], 131 MB
__device__ float g_pmax[B_ * NTILE * A_];
__device__ float g_psum[B_ * NTILE * A_];
__device__ float g_logZ[B_ * A_];

// folded weights (filled by init kernels each launch)
__device__ float  g_WC[64 * 9];          // conv2∘conv1 composite [oc][t], t=k1+k2
__device__ float  g_bC[64];              // composite conv bias (interior)
__device__ float2 g_we9[64 * 9];         // lin1∘conv composite, jp-paired
__device__ float2 g_bep[64];             // folded bias pairs
__device__ float  g_w2t[128 * 128];      // [(k*2+h)*64 + txw*4 + jj] = w2[j][k]
__device__ float  g_difft[128 * 64];     // [k*64 + a] = diff[a][k]
__device__ float  g_hsb[B_ * 4 * 128];   // exact boundary h1 (relu'd)

// ---------------- shared memory layout (bytes) ------------------------------
#define SM_BINC  0                 // 144 floats (576 B)
#define SM_WE9   576               // u64[576] = 4608 B
#define SM_BEP   5184              // float2[64] = 512 B
#define SM_RED   5696              // float[16][64] = 4096 B
#define SM_BM    9792              // float[64] = 256 B
#define SM_HS    32768             // float[128][128] = 65536
#define SM_WBUF  98304             // 16384 floats = 65536 (w2t)
#define SM_DIFF  163840            // 8192 floats = 32768 (difft)
#define SM_TOTAL 196608

// ---- packed f32x2 helpers ----
__device__ __forceinline__ u64 pk2(float x) {
    u64 r; asm("mov.b64 %0, {%1, %1};" : "=l"(r) : "f"(x)); return r;
}
__device__ __forceinline__ void fma2(u64& d, u64 a, u64 b) {
    asm("fma.rn.f32x2 %0, %1, %2, %0;" : "+l"(d) : "l"(a), "l"(b));
}
__device__ __forceinline__ float2 up(u64 v) {
    float2 f; asm("mov.b64 {%0, %1}, %2;" : "=f"(f.x), "=f"(f.y) : "l"(v)); return f;
}

// ---- init1: fold conv1 into conv2 (interior composite) ---------------------
__global__ void init1_kernel(const float* __restrict__ w1, const float* __restrict__ b1,
                             const float* __restrict__ w2, const float* __restrict__ b2)
{
    int t = threadIdx.x;
    if (t < 576) {
        int oc = t / 9, tt = t % 9;
        float s = 0.f;
        for (int ic = 0; ic < 32; ic++) {
            int klo = tt - 4 > 0 ? tt - 4 : 0;
            int khi = tt < 4 ? tt : 4;
            for (int k = klo; k <= khi; k++)
                s += w2[(oc * 32 + ic) * 5 + k] * w1[ic * 5 + (tt - k)];
        }
        g_WC[t] = s;
    } else if (t < 640) {
        int oc = t - 576;
        float s = b2[oc];
        for (int ic = 0; ic < 32; ic++) {
            float ws = 0.f;
            for (int k = 0; k < 5; k++) ws += w2[(oc * 32 + ic) * 5 + k];
            s += b1[ic] * ws;
        }
        g_bC[oc] = s;
    }
}

// ---- init2: fold lin1 into composite; transpose w2, diff -------------------
__global__ void init2_kernel(const float* __restrict__ l1w, const float* __restrict__ l1b,
                             const float* __restrict__ l2w, const float* __restrict__ diff)
{
    int t = blockIdx.x * blockDim.x + threadIdx.x;
    if (t < 576) {
        int jp = t / 9, tt = t % 9;
        float sx = 0.f, sy = 0.f;
        for (int oc = 0; oc < 64; oc++) {
            float wc = g_WC[oc * 9 + tt];
            sx += l1w[(2 * jp)     * 64 + oc] * wc;
            sy += l1w[(2 * jp + 1) * 64 + oc] * wc;
        }
        g_we9[t] = make_float2(sx, sy);
    } else if (t < 640) {
        int jp = t - 576;
        float sx = l1b[2 * jp], sy = l1b[2 * jp + 1];
        for (int oc = 0; oc < 64; oc++) {
            float bc = g_bC[oc];
            sx += l1w[(2 * jp)     * 64 + oc] * bc;
            sy += l1w[(2 * jp + 1) * 64 + oc] * bc;
        }
        g_bep[jp] = make_float2(sx, sy);
    }
    if (t >= 1024 && t < 1024 + 128 * 128) {   // w2t
        int idx = t - 1024;
        int j = idx >> 7, k = idx & 127;
        int h = (j >> 2) & 1, txw = j >> 3, jj = j & 3;
        g_w2t[(k * 2 + h) * 64 + txw * 4 + jj] = l2w[j * 128 + k];
    }
    if (t >= 17408 && t < 17408 + 64 * 128) {  // difft
        int idx = t - 17408;
        int a = idx >> 7, k = idx & 127;
        g_difft[k * 64 + a] = diff[a * 128 + k];
    }
}

// ---- init3: exact boundary h1 columns (l = 0,1,L-2,L-1) per b --------------
__global__ void boundary_kernel(const float* __restrict__ binc,
                                const float* __restrict__ w1, const float* __restrict__ b1,
                                const float* __restrict__ w2, const float* __restrict__ b2,
                                const float* __restrict__ l1w, const float* __restrict__ l1b)
{
    __shared__ float c1L[32][4], c1R[32][4];
    __shared__ float c2b[4][64];
    __shared__ float xL[8], xR[8];
    int b = blockIdx.x, t = threadIdx.x;
    const float* x = binc + b * L_;
    if (t < 6)             xL[t]     = x[t];
    if (t >= 8 && t < 14)  xR[t - 8] = x[L_ - 6 + t - 8];
    __syncthreads();
    {
        int ic = t >> 2, p = t & 3;
        float aL = b1[ic], aR = b1[ic];
        #pragma unroll
        for (int k = 0; k < 5; k++) {
            float w = w1[ic * 5 + k];
            int qL = p + k - 2;
            if (qL >= 0) aL += w * xL[qL];
            int qR = p + k;
            if (qR < 6) aR += w * xR[qR];
        }
        c1L[ic][p] = aL; c1R[ic][p] = aR;
    }
    __syncthreads();
    {
        int oc = t & 63, li0 = t >> 6;
        #pragma unroll
        for (int e = 0; e < 2; e++) {
            int li = li0 + 2 * e;
            float acc = b2[oc];
            for (int ic = 0; ic < 32; ic++) {
                const float* wr = &w2[(oc * 32 + ic) * 5];
                if (li == 0) {
                    #pragma unroll
                    for (int k = 2; k < 5; k++) acc += wr[k] * c1L[ic][k - 2];
                } else if (li == 1) {
                    #pragma unroll
                    for (int k = 1; k < 5; k++) acc += wr[k] * c1L[ic][k - 1];
                } else if (li == 2) {
                    #pragma unroll
                    for (int k = 0; k < 4; k++) acc += wr[k] * c1R[ic][k];
                } else {
                    #pragma unroll
                    for (int k = 0; k < 3; k++) acc += wr[k] * c1R[ic][k + 1];
                }
            }
            c2b[li][oc] = acc;
        }
    }
    __syncthreads();
    {
        int j = t;
        #pragma unroll
        for (int li = 0; li < 4; li++) {
            float h = l1b[j];
            for (int oc = 0; oc < 64; oc++) h += l1w[j * 64 + oc] * c2b[li][oc];
            g_hsb[b * 512 + li * 128 + j] = fmaxf(h, 0.f);
        }
    }
}

__global__ void __launch_bounds__(NTHR, 1)
fused_kernel(const float* __restrict__ binc_g,
             const float* __restrict__ l2b_g,
             const float* __restrict__ baseline_g,
             const int*   __restrict__ regions_oi_g)
{
    extern __shared__ char smem[];
    float* sbinc = (float*)(smem + SM_BINC);
    u64*   swe   = (u64*)(smem + SM_WE9);
    u64*   sbep  = (u64*)(smem + SM_BEP);
    float* red   = (float*)(smem + SM_RED);
    float* bm    = (float*)(smem + SM_BM);
    float* hs    = (float*)(smem + SM_HS);     // [128][128]; h1 then h2
    float* wbuf  = (float*)(smem + SM_WBUF);   // w2t
    float* sdiff = (float*)(smem + SM_DIFF);   // difft

    const int t       = threadIdx.x;
    const int tileIdx = blockIdx.x;
    const int b       = blockIdx.y;
    const int l0      = tileIdx * TILE;

    // ---- coalesced staging: w2t, difft, we9/bep, bincounts halo ----
    {
        const float4* s = (const float4*)g_w2t;
        float4*       d = (float4*)wbuf;
        #pragma unroll
        for (int i = 0; i < 16; i++) d[t + i * NTHR] = s[t + i * NTHR];
        const float4* s2 = (const float4*)g_difft;
        float4*       d2 = (float4*)sdiff;
        #pragma unroll
        for (int i = 0; i < 8; i++) d2[t + i * NTHR] = s2[t + i * NTHR];
    }
    for (int i = t; i < 288; i += NTHR)
        ((float4*)swe)[i] = ((const float4*)g_we9)[i];
    if (t < 32) ((float4*)sbep)[t] = ((const float4*)g_bep)[t];
    if (t < TILE + 8) {
        int l = l0 - 4 + t;
        sbinc[t] = (l >= 0 && l < L_) ? binc_g[b * L_ + l] : 0.f;
    }
    __syncthreads();

    // ---- composite conv9: hs[j][l] = relu(bE[j] + sum_t WE[j][t]*x[l+t-4]) ----
    for (int item = t; item < 64 * 16; item += NTHR) {
        int jp = item >> 4;
        int lb = (item & 15) * 8;
        u64 binit = sbep[jp];
        u64 acc[8];
        #pragma unroll
        for (int i = 0; i < 8; i++) acc[i] = binit;
        float xs[16];
        #pragma unroll
        for (int q = 0; q < 4; q++) {
            float4 v = *(const float4*)&sbinc[lb + q * 4];
            xs[q * 4] = v.x; xs[q * 4 + 1] = v.y; xs[q * 4 + 2] = v.z; xs[q * 4 + 3] = v.w;
        }
        u64 xv[16];
        #pragma unroll
        for (int i = 0; i < 16; i++) xv[i] = pk2(xs[i]);
        const u64* wp = &swe[jp * 9];
        #pragma unroll
        for (int k = 0; k < 9; k++) {
            u64 w = wp[k];
            #pragma unroll
            for (int i = 0; i < 8; i++) fma2(acc[i], xv[i + k], w);
        }
        float r0[8], r1[8];
        #pragma unroll
        for (int i = 0; i < 8; i++) {
            float2 v = up(acc[i]);
            r0[i] = fmaxf(v.x, 0.f); r1[i] = fmaxf(v.y, 0.f);
        }
        *(float4*)&hs[(2 * jp)     * 128 + lb]     = make_float4(r0[0], r0[1], r0[2], r0[3]);
        *(float4*)&hs[(2 * jp)     * 128 + lb + 4] = make_float4(r0[4], r0[5], r0[6], r0[7]);
        *(float4*)&hs[(2 * jp + 1) * 128 + lb]     = make_float4(r1[0], r1[1], r1[2], r1[3]);
        *(float4*)&hs[(2 * jp + 1) * 128 + lb + 4] = make_float4(r1[4], r1[5], r1[6], r1[7]);
    }
    // exact boundary columns override (l = 0,1 and L-2,L-1)
    if (tileIdx == 0) {
        __syncthreads();
        int li = t >> 7, j = t & 127;
        hs[j * 128 + li] = g_hsb[b * 512 + li * 128 + j];
    } else if (tileIdx == NTILE - 1) {
        __syncthreads();
        int li = t >> 7, j = t & 127;       // l = 1998,1999 -> local 78,79
        hs[j * 128 + 78 + li] = g_hsb[b * 512 + (2 + li) * 128 + j];
    }
    __syncthreads();

    // ---- register-tiled GEMMs: 16x16 threads, 8x8 tiles, j-packed ----
    const int tx = t & 15, ty = t >> 4;
    const int row0 = ty * 8;
    const int col0 = tx * 8;

    // GEMM2 (K=128): h2 = relu(h1^T w2^T + b2) — software-pipelined
    u64 accB[8][4];
    #pragma unroll
    for (int i = 0; i < 8; i++)
        #pragma unroll
        for (int p = 0; p < 4; p++) accB[i][p] = 0ull;
    {
        float4 a0 = *(const float4*)&hs[row0];
        float4 a1 = *(const float4*)&hs[row0 + 4];
        ulonglong2 B0 = *(const ulonglong2*)&wbuf[tx * 4];
        ulonglong2 B1 = *(const ulonglong2*)&wbuf[64 + tx * 4];
        #pragma unroll 4
        for (int k = 0; k < 128; k++) {
            float4 ca0 = a0, ca1 = a1;
            ulonglong2 cB0 = B0, cB1 = B1;
            int kn = k < 127 ? k + 1 : 127;
            a0 = *(const float4*)&hs[kn * 128 + row0];
            a1 = *(const float4*)&hs[kn * 128 + row0 + 4];
            B0 = *(const ulonglong2*)&wbuf[(kn * 2 + 0) * 64 + tx * 4];
            B1 = *(const ulonglong2*)&wbuf[(kn * 2 + 1) * 64 + tx * 4];
            u64 av2[8] = {pk2(ca0.x), pk2(ca0.y), pk2(ca0.z), pk2(ca0.w),
                          pk2(ca1.x), pk2(ca1.y), pk2(ca1.z), pk2(ca1.w)};
            u64 bv2[4] = {cB0.x, cB0.y, cB1.x, cB1.y};
            #pragma unroll
            for (int i = 0; i < 8; i++)
                #pragma unroll
                for (int p = 0; p < 4; p++) fma2(accB[i][p], av2[i], bv2[p]);
        }
    }
    __syncthreads();

    {
        #pragma unroll
        for (int p = 0; p < 4; p++) {
            float bx = l2b_g[col0 + 2 * p];
            float by = l2b_g[col0 + 2 * p + 1];
            #pragma unroll
            for (int i = 0; i < 8; i++) {
                float2 v = up(accB[i][p]);
                hs[(col0 + 2 * p)     * 128 + row0 + i] = fmaxf(v.x + bx, 0.f);
                hs[(col0 + 2 * p + 1) * 128 + row0 + i] = fmaxf(v.y + by, 0.f);
            }
        }
    }
    __syncthreads();

    // GEMM3 (K=128, N=64): u = h2^T diff^T + baseline — software-pipelined
    const int col3 = tx * 4;
    u64 accC[8][2];
    #pragma unroll
    for (int i = 0; i < 8; i++)
        #pragma unroll
        for (int p = 0; p < 2; p++) accC[i][p] = 0ull;
    {
        float4 a0 = *(const float4*)&hs[row0];
        float4 a1 = *(const float4*)&hs[row0 + 4];
        ulonglong2 B0 = *(const ulonglong2*)&sdiff[tx * 4];
        #pragma unroll 4
        for (int k = 0; k < 128; k++) {
            float4 ca0 = a0, ca1 = a1;
            ulonglong2 cB0 = B0;
            int kn = k < 127 ? k + 1 : 127;
            a0 = *(const float4*)&hs[kn * 128 + row0];
            a1 = *(const float4*)&hs[kn * 128 + row0 + 4];
            B0 = *(const ulonglong2*)&sdiff[kn * 64 + tx * 4];
            u64 av2[8] = {pk2(ca0.x), pk2(ca0.y), pk2(ca0.z), pk2(ca0.w),
                          pk2(ca1.x), pk2(ca1.y), pk2(ca1.z), pk2(ca1.w)};
            u64 bv2[2] = {cB0.x, cB0.y};
            #pragma unroll
            for (int i = 0; i < 8; i++)
                #pragma unroll
                for (int p = 0; p < 2; p++) fma2(accC[i][p], av2[i], bv2[p]);
        }
    }

    // epilogue: add baseline, write u, per-tile logsumexp partials
    const int r = regions_oi_g[b];
    float bval[8];
    bool  valid[8];
    #pragma unroll
    for (int i = 0; i < 8; i++) {
        int gl = l0 + row0 + i;
        valid[i] = (gl < L_);
        bval[i]  = valid[i] ? baseline_g[r * L_ + gl] : 0.f;
    }
    float uv[8][4];
    #pragma unroll
    for (int i = 0; i < 8; i++) {
        #pragma unroll
        for (int p = 0; p < 2; p++) {
            float2 v = up(accC[i][p]);
            uv[i][2 * p]     = v.x + bval[i];
            uv[i][2 * p + 1] = v.y + bval[i];
        }
    }
    float mloc[4] = {-FLT_MAX, -FLT_MAX, -FLT_MAX, -FLT_MAX};
    #pragma unroll
    for (int i = 0; i < 8; i++) {
        if (!valid[i]) continue;
        int gl = l0 + row0 + i;
        *(float4*)&g_U[(size_t)(b * L_ + gl) * A_ + col3] =
            make_float4(uv[i][0], uv[i][1], uv[i][2], uv[i][3]);
        #pragma unroll
        for (int j = 0; j < 4; j++) mloc[j] = fmaxf(mloc[j], uv[i][j]);
    }
    #pragma unroll
    for (int j = 0; j < 4; j++) red[ty * 64 + col3 + j] = mloc[j];
    __syncthreads();
    if (t < 64) {
        float m = -FLT_MAX;
        #pragma unroll
        for (int q = 0; q < 16; q++) m = fmaxf(m, red[q * 64 + t]);
        bm[t] = m;
    }
    __syncthreads();
    float bmj[4];
    #pragma unroll
    for (int j = 0; j < 4; j++) bmj[j] = bm[col3 + j];
    float sloc[4] = {0.f, 0.f, 0.f, 0.f};
    #pragma unroll
    for (int i = 0; i < 8; i++) {
        if (!valid[i]) continue;
        #pragma unroll
        for (int j = 0; j < 4; j++) sloc[j] += __expf(uv[i][j] - bmj[j]);
    }
    #pragma unroll
    for (int j = 0; j < 4; j++) red[ty * 64 + col3 + j] = sloc[j];
    __syncthreads();
    if (t < 64) {
        float s = 0.f;
        #pragma unroll
        for (int q = 0; q < 16; q++) s += red[q * 64 + t];
        g_pmax[(b * NTILE + tileIdx) * A_ + t] = bm[t];
        g_psum[(b * NTILE + tileIdx) * A_ + t] = s;
    }
}

__global__ void combine_kernel()
{
    int id = blockIdx.x * blockDim.x + threadIdx.x;
    if (id >= B_ * A_) return;
    int b = id >> 6, a = id & 63;
    float m = -FLT_MAX;
    #pragma unroll
    for (int q = 0; q < NTILE; q++)
        m = fmaxf(m, g_pmax[(b * NTILE + q) * A_ + a]);
    float s = 0.f;
    #pragma unroll
    for (int q = 0; q < NTILE; q++)
        s += g_psum[(b * NTILE + q) * A_ + a] * __expf(g_pmax[(b * NTILE + q) * A_ + a] - m);
    g_logZ[b * A_ + a] = m + logf(s);
}

__global__ void gather_kernel(const int* __restrict__ labels,
                              const int* __restrict__ cell_ix,
                              const int* __restrict__ region_ix,
                              const int* __restrict__ binixs,
                              float* __restrict__ out, int nf)
{
    int f = blockIdx.x * blockDim.x + threadIdx.x;
    if (f >= nf) return;
    int a = labels[cell_ix[f]];
    int b = region_ix[f];
    int l = binixs[f];
    out[f] = g_U[(size_t)(b * L_ + l) * A_ + a] - g_logZ[b * A_ + a]
           + 5.545177444479562f;  // + log(B=256)
}

extern "C" void kernel_launch(void* const* d_in, const int* in_sizes, int n_in,
                              void* d_out, int out_size)
{
    const float* bincounts  = (const float*)d_in[0];
    const float* conv1_w    = (const float*)d_in[1];
    const float* conv1_b    = (const float*)d_in[2];
    const float* conv2_w    = (const float*)d_in[3];
    const float* conv2_b    = (const float*)d_in[4];
    const float* lin1_w     = (const float*)d_in[5];
    const float* lin1_b     = (const float*)d_in[6];
    const float* lin2_w     = (const float*)d_in[7];
    const float* lin2_b     = (const float*)d_in[8];
    const float* baseline   = (const float*)d_in[9];
    const float* diff       = (const float*)d_in[10];
    const int*   regions_oi = (const int*)d_in[11];
    const int*   labels     = (const int*)d_in[12];
    const int*   cell_ix    = (const int*)d_in[13];
    const int*   region_ix  = (const int*)d_in[14];
    const int*   binixs     = (const int*)d_in[15];
    float* out = (float*)d_out;
    int nf = in_sizes[13];

    cudaFuncSetAttribute(fused_kernel,
                         cudaFuncAttributeMaxDynamicSharedMemorySize, SM_TOTAL);

    init1_kernel<<<1, 640>>>(conv1_w, conv1_b, conv2_w, conv2_b);
    init2_kernel<<<100, 256>>>(lin1_w, lin1_b, lin2_w, diff);
    boundary_kernel<<<B_, 128>>>(bincounts, conv1_w, conv1_b, conv2_w, conv2_b,
                                 lin1_w, lin1_b);

    dim3 grid(NTILE, B_);
    fused_kernel<<<grid, NTHR, SM_TOTAL>>>(bincounts, lin2_b, baseline, regions_oi);
    combine_kernel<<<(B_ * A_ + 255) / 256, 256>>>();
    gather_kernel<<<(nf + 255) / 256, 256>>>(labels, cell_ix, region_ix,
                                             binixs, out, nf);
}

// round 11
// speedup vs baseline: 2.1103x; 2.1103x over previous
#include <cuda_runtime.h>
#include <cuda_bf16.h>
#include <float.h>
#include <math.h>

#define A_  64
#define B_  256
#define L_  2000
#define TILE 128
#define NTILE 16
#define NTHR 256

typedef unsigned long long u64;
typedef unsigned int u32;

__device__ float g_U[B_ * L_ * A_];
__device__ float g_pmax[B_ * NTILE * A_];
__device__ float g_psum[B_ * NTILE * A_];
__device__ float g_logZ[B_ * A_];

__device__ float  g_WC[64 * 9];
__device__ float  g_bC[64];
__device__ float2 g_we9[64 * 9];
__device__ float2 g_bep[64];
__device__ float  g_hsb[B_ * 4 * 128];
// bf16 hi/lo weights, [n][k] rows padded to 136 bf16 (272B stride)
__device__ __align__(16) u32 g_w2h[128 * 68], g_w2l[128 * 68];
__device__ __align__(16) u32 g_dfh[64 * 68],  g_dfl[64 * 68];

// ---------------- shared memory layout (bytes, all 16B aligned) -------------
#define SM_BINC  0         // 576
#define SM_BEP   576       // 512
#define SM_L2B   1088      // 512
#define SM_BM    1600      // 256
#define SM_WE9   1856      // 4608
#define SM_AH    6464      // 34816  (h1/h2 hi; later ux[64][129] fp32)
#define SM_AL    41280     // 34816  (lo)
#define SM_W2H   76096     // 34816
#define SM_W2L   110912    // 34816
#define SM_DFH   145728    // 17408
#define SM_DFL   163136    // 17408
#define SM_TOTAL 180544

__device__ __forceinline__ u64 pk2(float x){u64 r;asm("mov.b64 %0,{%1,%1};":"=l"(r):"f"(x));return r;}
__device__ __forceinline__ void fma2(u64&d,u64 a,u64 b){asm("fma.rn.f32x2 %0,%1,%2,%0;":"+l"(d):"l"(a),"l"(b));}
__device__ __forceinline__ float2 up(u64 v){float2 f;asm("mov.b64 {%0,%1},%2;":"=f"(f.x),"=f"(f.y):"l"(v));return f;}
__device__ __forceinline__ u32 pkbf(float x,float y){__nv_bfloat162 t=__floats2bfloat162_rn(x,y);return *(u32*)&t;}
__device__ __forceinline__ void split2(float x,float y,u32&hi,u32&lo){
    hi=pkbf(x,y);
    float fx=__uint_as_float(hi<<16), fy=__uint_as_float(hi&0xffff0000u);
    lo=pkbf(x-fx,y-fy);
}
__device__ __forceinline__ u32 stosh(const void*p){u32 a;asm("{ .reg .u64 t; cvta.to.shared.u64 t,%1; cvt.u32.u64 %0,t; }":"=r"(a):"l"(p));return a;}
__device__ __forceinline__ void ldsm4(u32 addr,u32&r0,u32&r1,u32&r2,u32&r3){
    asm volatile("ldmatrix.sync.aligned.m8n8.x4.shared.b16 {%0,%1,%2,%3},[%4];"
        :"=r"(r0),"=r"(r1),"=r"(r2),"=r"(r3):"r"(addr));
}
__device__ __forceinline__ void mma16816(float* c,u32 a0,u32 a1,u32 a2,u32 a3,u32 b0,u32 b1){
    asm volatile("mma.sync.aligned.m16n8k16.row.col.f32.bf16.bf16.f32 "
        "{%0,%1,%2,%3},{%4,%5,%6,%7},{%8,%9},{%0,%1,%2,%3};"
        :"+f"(c[0]),"+f"(c[1]),"+f"(c[2]),"+f"(c[3])
        :"r"(a0),"r"(a1),"r"(a2),"r"(a3),"r"(b0),"r"(b1));
}

__global__ void init1_kernel(const float* w1, const float* b1, const float* w2, const float* b2)
{
    int t = threadIdx.x;
    if (t < 576) {
        int oc = t / 9, tt = t % 9;
        float s = 0.f;
        for (int ic = 0; ic < 32; ic++) {
            int klo = tt - 4 > 0 ? tt - 4 : 0, khi = tt < 4 ? tt : 4;
            for (int k = klo; k <= khi; k++)
                s += w2[(oc * 32 + ic) * 5 + k] * w1[ic * 5 + (tt - k)];
        }
        g_WC[t] = s;
    } else if (t < 640) {
        int oc = t - 576;
        float s = b2[oc];
        for (int ic = 0; ic < 32; ic++) {
            float ws = 0.f;
            for (int k = 0; k < 5; k++) ws += w2[(oc * 32 + ic) * 5 + k];
            s += b1[ic] * ws;
        }
        g_bC[oc] = s;
    }
}

__global__ void init2_kernel(const float* l1w, const float* l1b,
                             const float* l2w, const float* diff)
{
    int t = blockIdx.x * blockDim.x + threadIdx.x;
    if (t < 576) {
        int jp = t / 9, tt = t % 9;
        float sx = 0.f, sy = 0.f;
        for (int oc = 0; oc < 64; oc++) {
            float wc = g_WC[oc * 9 + tt];
            sx += l1w[(2 * jp) * 64 + oc] * wc;
            sy += l1w[(2 * jp + 1) * 64 + oc] * wc;
        }
        g_we9[t] = make_float2(sx, sy);
    } else if (t < 640) {
        int jp = t - 576;
        float sx = l1b[2 * jp], sy = l1b[2 * jp + 1];
        for (int oc = 0; oc < 64; oc++) {
            float bc = g_bC[oc];
            sx += l1w[(2 * jp) * 64 + oc] * bc;
            sy += l1w[(2 * jp + 1) * 64 + oc] * bc;
        }
        g_bep[jp] = make_float2(sx, sy);
    }
    if (t < 128 * 128) {          // w2[n=j][k]
        int n = t >> 7, k = t & 127;
        float w = l2w[t];
        __nv_bfloat16 hh = __float2bfloat16(w);
        __nv_bfloat16 ll = __float2bfloat16(w - __bfloat162float(hh));
        ((__nv_bfloat16*)g_w2h)[n * 136 + k] = hh;
        ((__nv_bfloat16*)g_w2l)[n * 136 + k] = ll;
    }
    if (t < 64 * 128) {           // diff[n=a][k=j]
        int n = t >> 7, k = t & 127;
        float w = diff[t];
        __nv_bfloat16 hh = __float2bfloat16(w);
        __nv_bfloat16 ll = __float2bfloat16(w - __bfloat162float(hh));
        ((__nv_bfloat16*)g_dfh)[n * 136 + k] = hh;
        ((__nv_bfloat16*)g_dfl)[n * 136 + k] = ll;
    }
}

__global__ void boundary_kernel(const float* binc, const float* w1, const float* b1,
                                const float* w2, const float* b2,
                                const float* l1w, const float* l1b)
{
    __shared__ float c1L[32][4], c1R[32][4], c2b[4][64], xL[8], xR[8];
    int b = blockIdx.x, t = threadIdx.x;
    const float* x = binc + b * L_;
    if (t < 6)            xL[t]     = x[t];
    if (t >= 8 && t < 14) xR[t - 8] = x[L_ - 6 + t - 8];
    __syncthreads();
    {
        int ic = t >> 2, p = t & 3;
        float aL = b1[ic], aR = b1[ic];
        #pragma unroll
        for (int k = 0; k < 5; k++) {
            float w = w1[ic * 5 + k];
            int qL = p + k - 2; if (qL >= 0) aL += w * xL[qL];
            int qR = p + k;     if (qR < 6)  aR += w * xR[qR];
        }
        c1L[ic][p] = aL; c1R[ic][p] = aR;
    }
    __syncthreads();
    {
        int oc = t & 63, li0 = t >> 6;
        #pragma unroll
        for (int e = 0; e < 2; e++) {
            int li = li0 + 2 * e;
            float acc = b2[oc];
            for (int ic = 0; ic < 32; ic++) {
                const float* wr = &w2[(oc * 32 + ic) * 5];
                if (li == 0)      { for (int k = 2; k < 5; k++) acc += wr[k] * c1L[ic][k - 2]; }
                else if (li == 1) { for (int k = 1; k < 5; k++) acc += wr[k] * c1L[ic][k - 1]; }
                else if (li == 2) { for (int k = 0; k < 4; k++) acc += wr[k] * c1R[ic][k]; }
                else              { for (int k = 0; k < 3; k++) acc += wr[k] * c1R[ic][k + 1]; }
            }
            c2b[li][oc] = acc;
        }
    }
    __syncthreads();
    {
        int j = t;
        #pragma unroll
        for (int li = 0; li < 4; li++) {
            float h = l1b[j];
            for (int oc = 0; oc < 64; oc++) h += l1w[j * 64 + oc] * c2b[li][oc];
            g_hsb[b * 512 + li * 128 + j] = fmaxf(h, 0.f);
        }
    }
}

__global__ void __launch_bounds__(NTHR, 1)
fused_kernel(const float* __restrict__ binc_g, const float* __restrict__ l2b_g,
             const float* __restrict__ baseline_g, const int* __restrict__ regions_oi_g)
{
    extern __shared__ char smem[];
    const int t = threadIdx.x, wid = t >> 5, lane = t & 31;
    const int tileIdx = blockIdx.x, b = blockIdx.y;
    const int l0 = tileIdx * TILE;
    const u32 sb = stosh(smem);

    // ---- staging: weights (hi/lo), we9, bep, l2b, bincounts halo ----
    {
        float4* dh = (float4*)(smem + SM_W2H); const float4* shh = (const float4*)g_w2h;
        float4* dl = (float4*)(smem + SM_W2L); const float4* sll = (const float4*)g_w2l;
        for (int i = t; i < 2176; i += NTHR) { dh[i] = shh[i]; dl[i] = sll[i]; }
        float4* eh = (float4*)(smem + SM_DFH); const float4* gh = (const float4*)g_dfh;
        float4* el = (float4*)(smem + SM_DFL); const float4* gl = (const float4*)g_dfl;
        for (int i = t; i < 1088; i += NTHR) { eh[i] = gh[i]; el[i] = gl[i]; }
        float4* d = (float4*)(smem + SM_WE9); const float4* s = (const float4*)g_we9;
        for (int i = t; i < 288; i += NTHR) d[i] = s[i];
    }
    if (t < 32)  ((float4*)(smem + SM_BEP))[t] = ((const float4*)g_bep)[t];
    if (t < 128) ((float*)(smem + SM_L2B))[t]  = l2b_g[t];
    if (t < 136) {
        int l = l0 - 4 + t;
        ((float*)(smem + SM_BINC))[t] = (l >= 0 && l < L_) ? binc_g[b * L_ + l] : 0.f;
    }
    __syncthreads();

    // ---- conv9 -> h1 split into AH/AL bf16 [l][k], 272B row stride ----
    {
        const u64* swe = (const u64*)(smem + SM_WE9);
        const u64* sbep = (const u64*)(smem + SM_BEP);
        const float* sbinc = (const float*)(smem + SM_BINC);
        int jp = t & 63, lbq = t >> 6;
        u64 wp[9];
        #pragma unroll
        for (int k = 0; k < 9; k++) wp[k] = swe[jp * 9 + k];
        u64 bini = sbep[jp];
        #pragma unroll
        for (int q = 0; q < 4; q++) {
            int lb = (lbq + 4 * q) * 8;
            u64 acc[8];
            #pragma unroll
            for (int i = 0; i < 8; i++) acc[i] = bini;
            u64 xv[16];
            #pragma unroll
            for (int g = 0; g < 4; g++) {
                float4 v = *(const float4*)&sbinc[lb + g * 4];
                xv[g*4] = pk2(v.x); xv[g*4+1] = pk2(v.y); xv[g*4+2] = pk2(v.z); xv[g*4+3] = pk2(v.w);
            }
            #pragma unroll
            for (int k = 0; k < 9; k++) {
                u64 w = wp[k];
                #pragma unroll
                for (int i = 0; i < 8; i++) fma2(acc[i], xv[i + k], w);
            }
            #pragma unroll
            for (int i = 0; i < 8; i++) {
                float2 v = up(acc[i]);
                u32 hi, lo; split2(fmaxf(v.x, 0.f), fmaxf(v.y, 0.f), hi, lo);
                u32 ad = (u32)((lb + i) * 272 + jp * 4);
                *(u32*)(smem + SM_AH + ad) = hi;
                *(u32*)(smem + SM_AL + ad) = lo;
            }
        }
    }
    if (tileIdx == 0 || tileIdx == NTILE - 1) {
        __syncthreads();
        int li = t >> 7, k = t & 127;
        int l  = (tileIdx == 0) ? li : (78 + li);
        int hb = (tileIdx == 0) ? li : (2 + li);
        float v = g_hsb[b * 512 + hb * 128 + k];
        __nv_bfloat16 hh = __float2bfloat16(v);
        __nv_bfloat16 ll = __float2bfloat16(v - __bfloat162float(hh));
        *(__nv_bfloat16*)(smem + SM_AH + l * 272 + k * 2) = hh;
        *(__nv_bfloat16*)(smem + SM_AL + l * 272 + k * 2) = ll;
    }
    __syncthreads();

    // ---- warp tiling: 4 warps along M (32 rows), 2 along N ----
    const int m0 = (wid & 3) * 32;
    const u32 aoff = (u32)((m0 + (lane & 15)) * 272 + (lane >> 4) * 16);
    const u32 brow = (u32)(((lane >> 4) * 8 + (lane & 7)) * 272 + ((lane >> 3) & 1) * 16);

    // ==== GEMM2: h2 = relu(h1 @ w2^T + b2), M=128 N=128 K=128, 3-term split ====
    {
        const int n0 = (wid >> 2) * 64;
        float C[16][4];
        #pragma unroll
        for (int i = 0; i < 16; i++)
            #pragma unroll
            for (int j = 0; j < 4; j++) C[i][j] = 0.f;
        #pragma unroll 1
        for (int pass = 0; pass < 3; pass++) {
            u32 Ab = sb + (pass == 2 ? SM_AL : SM_AH) + aoff;
            u32 Bb = sb + (pass == 1 ? SM_W2L : SM_W2H) + (u32)(n0 * 272) + brow;
            #pragma unroll 1
            for (int ks = 0; ks < 8; ks++) {
                u32 kb = (u32)(ks * 32);
                u32 a0[4], a1[4], br[8][2];
                ldsm4(Ab + kb, a0[0], a0[1], a0[2], a0[3]);
                ldsm4(Ab + 16 * 272 + kb, a1[0], a1[1], a1[2], a1[3]);
                #pragma unroll
                for (int q = 0; q < 4; q++) {
                    u32 r0, r1, r2, r3;
                    ldsm4(Bb + (u32)(q * 16 * 272) + kb, r0, r1, r2, r3);
                    br[2*q][0] = r0; br[2*q][1] = r1; br[2*q+1][0] = r2; br[2*q+1][1] = r3;
                }
                #pragma unroll
                for (int nt = 0; nt < 8; nt++) {
                    mma16816(C[nt],     a0[0], a0[1], a0[2], a0[3], br[nt][0], br[nt][1]);
                    mma16816(C[8 + nt], a1[0], a1[1], a1[2], a1[3], br[nt][0], br[nt][1]);
                }
            }
        }
        __syncthreads();   // all warps done reading h1 tiles

        // epilogue2: bias+relu, re-split into AH/AL as h2 [l][k=j]
        const float* sl2b = (const float*)(smem + SM_L2B);
        #pragma unroll
        for (int mt = 0; mt < 2; mt++) {
            int la = m0 + mt * 16 + (lane >> 2);
            int lb2 = la + 8;
            #pragma unroll
            for (int nt = 0; nt < 8; nt++) {
                float* c = C[mt * 8 + nt];
                int j = n0 + nt * 8 + (lane & 3) * 2;
                float bj0 = sl2b[j], bj1 = sl2b[j + 1];
                u32 hi, lo;
                split2(fmaxf(c[0] + bj0, 0.f), fmaxf(c[1] + bj1, 0.f), hi, lo);
                *(u32*)(smem + SM_AH + la * 272 + j * 2) = hi;
                *(u32*)(smem + SM_AL + la * 272 + j * 2) = lo;
                split2(fmaxf(c[2] + bj0, 0.f), fmaxf(c[3] + bj1, 0.f), hi, lo);
                *(u32*)(smem + SM_AH + lb2 * 272 + j * 2) = hi;
                *(u32*)(smem + SM_AL + lb2 * 272 + j * 2) = lo;
            }
        }
    }
    __syncthreads();

    // ==== GEMM3: u = h2 @ diff^T + baseline, M=128 N=64 K=128 ====
    float C3[8][4];
    #pragma unroll
    for (int i = 0; i < 8; i++)
        #pragma unroll
        for (int j = 0; j < 4; j++) C3[i][j] = 0.f;
    const int n03 = (wid >> 2) * 32;
    #pragma unroll 1
    for (int pass = 0; pass < 3; pass++) {
        u32 Ab = sb + (pass == 2 ? SM_AL : SM_AH) + aoff;
        u32 Bb = sb + (pass == 1 ? SM_DFL : SM_DFH) + (u32)(n03 * 272) + brow;
        #pragma unroll 1
        for (int ks = 0; ks < 8; ks++) {
            u32 kb = (u32)(ks * 32);
            u32 a0[4], a1[4], br[4][2];
            ldsm4(Ab + kb, a0[0], a0[1], a0[2], a0[3]);
            ldsm4(Ab + 16 * 272 + kb, a1[0], a1[1], a1[2], a1[3]);
            #pragma unroll
            for (int q = 0; q < 2; q++) {
                u32 r0, r1, r2, r3;
                ldsm4(Bb + (u32)(q * 16 * 272) + kb, r0, r1, r2, r3);
                br[2*q][0] = r0; br[2*q][1] = r1; br[2*q+1][0] = r2; br[2*q+1][1] = r3;
            }
            #pragma unroll
            for (int nt = 0; nt < 4; nt++) {
                mma16816(C3[nt],     a0[0], a0[1], a0[2], a0[3], br[nt][0], br[nt][1]);
                mma16816(C3[4 + nt], a1[0], a1[1], a1[2], a1[3], br[nt][0], br[nt][1]);
            }
        }
    }
    __syncthreads();   // all warps done reading h2 -> AH region reusable

    // epilogue3: u = C3 + baseline; write g_U; LSE partials via ux transpose
    {
        const int rgn = regions_oi_g[b];
        float* ux = (float*)(smem + SM_AH);   // [64][129] fp32
        float* bmv = (float*)(smem + SM_BM);
        #pragma unroll
        for (int mt = 0; mt < 2; mt++) {
            int lr0 = m0 + mt * 16 + (lane >> 2);
            int lr1 = lr0 + 8;
            int gl0 = l0 + lr0, gl1 = l0 + lr1;
            bool v0 = gl0 < L_, v1 = gl1 < L_;
            float base0 = v0 ? baseline_g[rgn * L_ + gl0] : 0.f;
            float base1 = v1 ? baseline_g[rgn * L_ + gl1] : 0.f;
            #pragma unroll
            for (int nt = 0; nt < 4; nt++) {
                float* c = C3[mt * 4 + nt];
                int a = n03 + nt * 8 + (lane & 3) * 2;
                float u0 = v0 ? c[0] + base0 : -FLT_MAX;
                float u1 = v0 ? c[1] + base0 : -FLT_MAX;
                float u2 = v1 ? c[2] + base1 : -FLT_MAX;
                float u3 = v1 ? c[3] + base1 : -FLT_MAX;
                if (v0) *(float2*)&g_U[((size_t)(b * L_ + gl0)) * A_ + a] = make_float2(u0, u1);
                if (v1) *(float2*)&g_U[((size_t)(b * L_ + gl1)) * A_ + a] = make_float2(u2, u3);
                ux[a * 129 + lr0] = u0; ux[(a + 1) * 129 + lr0] = u1;
                ux[a * 129 + lr1] = u2; ux[(a + 1) * 129 + lr1] = u3;
            }
        }
        __syncthreads();
        if (t < 64) {
            float m = -FLT_MAX;
            const float* row = &ux[t * 129];
            #pragma unroll 8
            for (int i = 0; i < 128; i++) m = fmaxf(m, row[i]);
            bmv[t] = m;
        }
        __syncthreads();
        #pragma unroll
        for (int mt = 0; mt < 2; mt++) {
            int lr0 = m0 + mt * 16 + (lane >> 2);
            int lr1 = lr0 + 8;
            #pragma unroll
            for (int nt = 0; nt < 4; nt++) {
                int a = n03 + nt * 8 + (lane & 3) * 2;
                float m0v = bmv[a], m1v = bmv[a + 1];
                ux[a * 129 + lr0]       = __expf(ux[a * 129 + lr0]       - m0v);
                ux[(a + 1) * 129 + lr0] = __expf(ux[(a + 1) * 129 + lr0] - m1v);
                ux[a * 129 + lr1]       = __expf(ux[a * 129 + lr1]       - m0v);
                ux[(a + 1) * 129 + lr1] = __expf(ux[(a + 1) * 129 + lr1] - m1v);
            }
        }
        __syncthreads();
        if (t < 64) {
            float s = 0.f;
            const float* row = &ux[t * 129];
            #pragma unroll 8
            for (int i = 0; i < 128; i++) s += row[i];
            g_pmax[(b * NTILE + tileIdx) * A_ + t] = bmv[t];
            g_psum[(b * NTILE + tileIdx) * A_ + t] = s;
        }
    }
}

__global__ void combine_kernel()
{
    int id = blockIdx.x * blockDim.x + threadIdx.x;
    if (id >= B_ * A_) return;
    int b = id >> 6, a = id & 63;
    float m = -FLT_MAX;
    #pragma unroll
    for (int q = 0; q < NTILE; q++)
        m = fmaxf(m, g_pmax[(b * NTILE + q) * A_ + a]);
    float s = 0.f;
    #pragma unroll
    for (int q = 0; q < NTILE; q++)
        s += g_psum[(b * NTILE + q) * A_ + a] * __expf(g_pmax[(b * NTILE + q) * A_ + a] - m);
    g_logZ[b * A_ + a] = m + logf(s);
}

__global__ void gather_kernel(const int* __restrict__ labels, const int* __restrict__ cell_ix,
                              const int* __restrict__ region_ix, const int* __restrict__ binixs,
                              float* __restrict__ out, int nf)
{
    int f = blockIdx.x * blockDim.x + threadIdx.x;
    if (f >= nf) return;
    int a = labels[cell_ix[f]];
    int b = region_ix[f];
    int l = binixs[f];
    out[f] = g_U[(size_t)(b * L_ + l) * A_ + a] - g_logZ[b * A_ + a] + 5.545177444479562f;
}

extern "C" void kernel_launch(void* const* d_in, const int* in_sizes, int n_in,
                              void* d_out, int out_size)
{
    const float* bincounts  = (const float*)d_in[0];
    const float* conv1_w    = (const float*)d_in[1];
    const float* conv1_b    = (const float*)d_in[2];
    const float* conv2_w    = (const float*)d_in[3];
    const float* conv2_b    = (const float*)d_in[4];
    const float* lin1_w     = (const float*)d_in[5];
    const float* lin1_b     = (const float*)d_in[6];
    const float* lin2_w     = (const float*)d_in[7];
    const float* lin2_b     = (const float*)d_in[8];
    const float* baseline   = (const float*)d_in[9];
    const float* diff       = (const float*)d_in[10];
    const int*   regions_oi = (const int*)d_in[11];
    const int*   labels     = (const int*)d_in[12];
    const int*   cell_ix    = (const int*)d_in[13];
    const int*   region_ix  = (const int*)d_in[14];
    const int*   binixs     = (const int*)d_in[15];
    float* out = (float*)d_out;
    int nf = in_sizes[13];

    cudaFuncSetAttribute(fused_kernel,
                         cudaFuncAttributeMaxDynamicSharedMemorySize, SM_TOTAL);

    init1_kernel<<<1, 640>>>(conv1_w, conv1_b, conv2_w, conv2_b);
    init2_kernel<<<64, 256>>>(lin1_w, lin1_b, lin2_w, diff);
    boundary_kernel<<<B_, 128>>>(bincounts, conv1_w, conv1_b, conv2_w, conv2_b,
                                 lin1_w, lin1_b);

    dim3 grid(NTILE, B_);
    fused_kernel<<<grid, NTHR, SM_TOTAL>>>(bincounts, lin2_b, baseline, regions_oi);
    combine_kernel<<<(B_ * A_ + 255) / 256, 256>>>();
    gather_kernel<<<(nf + 255) / 256, 256>>>(labels, cell_ix, region_ix,
                                             binixs, out, nf);
}